// round 3
// baseline (speedup 1.0000x reference)
#include <cuda_runtime.h>

// PrototypeField: B=262144 rows, D=256, C=128 classes.
// out[0] = 0.1 * (1 - mean cos_sim), out[1..32768] = new_v (C,D) row-major.
//
// Pass 1 (accum_kernel): single read of dirs. Each CTA (148 total, 1024 thr)
// takes a contiguous slice of rows. Warp w owns classes [4w, 4w+4): it scans
// the slice's labels with ballot, and for each of its rows loads 256 floats
// (2x LDG.128/lane), normalizes (warp allreduce + sqrt), and accumulates into
// 32 register accumulators. End: 4.85M spread REDG.F32 into g_sums/g_counts.
//
// Pass 2 (finalize_kernel): 1 CTA. Per class: batch_mean, EMA, renormalize,
// write new_v, and dot(sums_c, new_v_c); loss = 0.1*(1 - sum_dots/B).

#define DD 256
#define CC 128
#define GRID1 148
#define T1 1024
#define FULLM 0xFFFFFFFFu

__device__ float g_sums[CC * DD];
__device__ float g_counts[CC];

__global__ void zero_kernel() {
    int i = blockIdx.x * blockDim.x + threadIdx.x;
    if (i < CC * DD) g_sums[i] = 0.0f;
    else if (i < CC * DD + CC) g_counts[i - CC * DD] = 0.0f;
}

#define ACC4(a, b) do { (a).x += (b).x; (a).y += (b).y; (a).z += (b).z; (a).w += (b).w; } while (0)

__global__ __launch_bounds__(T1, 1) void accum_kernel(
    const float* __restrict__ dirs,
    const int* __restrict__ labels,
    int B)
{
    __shared__ int labs[1824];

    const int tid  = threadIdx.x;
    const int wid  = tid >> 5;     // 0..31, owns classes [4*wid, 4*wid+4)
    const int lane = tid & 31;

    const int rows_per = (B + GRID1 - 1) / GRID1;   // 1772
    const int row0  = blockIdx.x * rows_per;
    const int nrows = min(rows_per, B - row0);
    if (nrows <= 0) return;

    for (int i = tid; i < nrows; i += T1) labs[i] = labels[row0 + i];
    __syncthreads();

    float4 z = make_float4(0.f, 0.f, 0.f, 0.f);
    float4 A0l = z, A0h = z, A1l = z, A1h = z, A2l = z, A2h = z, A3l = z, A3h = z;
    int n0 = 0, n1 = 0, n2 = 0, n3 = 0;

    for (int base = 0; base < nrows; base += 32) {
        int r = base + lane;
        int lab = (r < nrows) ? labs[r] : -1;
        unsigned m = __ballot_sync(FULLM, (lab >> 2) == wid);
        while (m) {
            int j = __ffs(m) - 1;
            m &= m - 1;
            int labj = __shfl_sync(FULLM, lab, j);
            long long row = (long long)(row0 + base + j);
            const float4* rp = (const float4*)(dirs + row * (long long)DD);
            float4 v0 = __ldg(rp + lane);
            float4 v1 = __ldg(rp + lane + 32);

            float s = v0.x * v0.x + v0.y * v0.y + v0.z * v0.z + v0.w * v0.w
                    + v1.x * v1.x + v1.y * v1.y + v1.z * v1.z + v1.w * v1.w;
            #pragma unroll
            for (int o = 16; o > 0; o >>= 1) s += __shfl_xor_sync(FULLM, s, o);
            float inv = 1.0f / fmaxf(sqrtf(s), 1e-12f);

            v0.x *= inv; v0.y *= inv; v0.z *= inv; v0.w *= inv;
            v1.x *= inv; v1.y *= inv; v1.z *= inv; v1.w *= inv;

            int k = labj & 3;
            if (k == 0)      { ACC4(A0l, v0); ACC4(A0h, v1); n0++; }
            else if (k == 1) { ACC4(A1l, v0); ACC4(A1h, v1); n1++; }
            else if (k == 2) { ACC4(A2l, v0); ACC4(A2h, v1); n2++; }
            else             { ACC4(A3l, v0); ACC4(A3h, v1); n3++; }
        }
    }

    #define WRITE_CLASS(K, AL, AH, NN) do {                                   \
        int c = (wid << 2) + (K);                                             \
        float* sp = g_sums + c * DD + (lane << 2);                            \
        atomicAdd(sp + 0,   (AL).x); atomicAdd(sp + 1,   (AL).y);             \
        atomicAdd(sp + 2,   (AL).z); atomicAdd(sp + 3,   (AL).w);             \
        atomicAdd(sp + 128, (AH).x); atomicAdd(sp + 129, (AH).y);             \
        atomicAdd(sp + 130, (AH).z); atomicAdd(sp + 131, (AH).w);             \
        if (lane == 0 && (NN) > 0) atomicAdd(&g_counts[c], (float)(NN));      \
    } while (0)

    WRITE_CLASS(0, A0l, A0h, n0);
    WRITE_CLASS(1, A1l, A1h, n1);
    WRITE_CLASS(2, A2l, A2h, n2);
    WRITE_CLASS(3, A3l, A3h, n3);
}

__global__ __launch_bounds__(1024, 1) void finalize_kernel(
    const float* __restrict__ v_class,
    const int* __restrict__ step_ptr,
    float* __restrict__ out,
    float Bf)
{
    __shared__ float wdots[32];
    const int tid  = threadIdx.x;
    const int wid  = tid >> 5;
    const int lane = tid & 31;

    float stepf = (float)(*step_ptr);
    float alpha = fminf(0.02f, stepf / (stepf + 50.0f));
    float oma = 1.0f - alpha;

    float warpDot = 0.0f;

    #pragma unroll
    for (int k = 0; k < 4; k++) {
        int c = (wid << 2) + k;
        const float4* sp = (const float4*)(g_sums + c * DD);
        float4 s0 = sp[lane];
        float4 s1 = sp[lane + 32];
        float cnt = g_counts[c];

        // batch_mean = sums / max(cnt, 1)
        float invc = 1.0f / fmaxf(cnt, 1.0f);
        float4 b0, b1;
        b0.x = s0.x * invc; b0.y = s0.y * invc; b0.z = s0.z * invc; b0.w = s0.w * invc;
        b1.x = s1.x * invc; b1.y = s1.y * invc; b1.z = s1.z * invc; b1.w = s1.w * invc;

        // normalize batch_mean
        float nb = b0.x * b0.x + b0.y * b0.y + b0.z * b0.z + b0.w * b0.w
                 + b1.x * b1.x + b1.y * b1.y + b1.z * b1.z + b1.w * b1.w;
        #pragma unroll
        for (int o = 16; o > 0; o >>= 1) nb += __shfl_xor_sync(FULLM, nb, o);
        float invb = 1.0f / fmaxf(sqrtf(nb), 1e-12f);

        const float4* vp = (const float4*)(v_class + c * DD);
        float4 vc0 = vp[lane];
        float4 vc1 = vp[lane + 32];

        // updated = normalize((1-a)*v + a*bm_n)
        float4 u0, u1;
        u0.x = oma * vc0.x + alpha * b0.x * invb;
        u0.y = oma * vc0.y + alpha * b0.y * invb;
        u0.z = oma * vc0.z + alpha * b0.z * invb;
        u0.w = oma * vc0.w + alpha * b0.w * invb;
        u1.x = oma * vc1.x + alpha * b1.x * invb;
        u1.y = oma * vc1.y + alpha * b1.y * invb;
        u1.z = oma * vc1.z + alpha * b1.z * invb;
        u1.w = oma * vc1.w + alpha * b1.w * invb;

        float nu = u0.x * u0.x + u0.y * u0.y + u0.z * u0.z + u0.w * u0.w
                 + u1.x * u1.x + u1.y * u1.y + u1.z * u1.z + u1.w * u1.w;
        #pragma unroll
        for (int o = 16; o > 0; o >>= 1) nu += __shfl_xor_sync(FULLM, nu, o);
        float invu = 1.0f / fmaxf(sqrtf(nu), 1e-12f);

        bool use = (cnt > 0.0f);
        float w0x = use ? u0.x * invu : vc0.x;
        float w0y = use ? u0.y * invu : vc0.y;
        float w0z = use ? u0.z * invu : vc0.z;
        float w0w = use ? u0.w * invu : vc0.w;
        float w1x = use ? u1.x * invu : vc1.x;
        float w1y = use ? u1.y * invu : vc1.y;
        float w1z = use ? u1.z * invu : vc1.z;
        float w1w = use ? u1.w * invu : vc1.w;

        // new_v -> out[1 + c*D + d]  (out+1 is not 16B aligned: scalar stores)
        float* op = out + 1 + c * DD + (lane << 2);
        op[0] = w0x; op[1] = w0y; op[2] = w0z; op[3] = w0w;
        op[128] = w1x; op[129] = w1y; op[130] = w1z; op[131] = w1w;

        // dot(sums_c, new_v_c)
        float p = s0.x * w0x + s0.y * w0y + s0.z * w0z + s0.w * w0w
                + s1.x * w1x + s1.y * w1y + s1.z * w1z + s1.w * w1w;
        #pragma unroll
        for (int o = 16; o > 0; o >>= 1) p += __shfl_xor_sync(FULLM, p, o);
        warpDot += p;
    }

    if (lane == 0) wdots[wid] = warpDot;
    __syncthreads();
    if (tid == 0) {
        float t = 0.0f;
        #pragma unroll
        for (int i = 0; i < 32; i++) t += wdots[i];
        out[0] = 0.1f * (1.0f - t / Bf);
    }
}

extern "C" void kernel_launch(void* const* d_in, const int* in_sizes, int n_in,
                              void* d_out, int out_size)
{
    const float* dirs    = (const float*)d_in[0];
    const float* v_class = (const float*)d_in[1];
    const int*   labels  = (const int*)d_in[2];
    const int*   step    = (const int*)d_in[3];
    int B = in_sizes[2];

    zero_kernel<<<(CC * DD + CC + 1023) / 1024, 1024>>>();
    accum_kernel<<<GRID1, T1>>>(dirs, labels, B);
    finalize_kernel<<<1, 1024>>>(v_class, step, (float*)d_out, (float)B);
}